// round 13
// baseline (speedup 1.0000x reference)
#include <cuda_runtime.h>
#include <cstdint>

// PEPS 6x6, D=3, B=16 — quadrant decomposition, cluster of 4 CTAs per config.
// rank 0=TL, 1=TR, 2=BL, 3=BR (mirrored -> identical code per quadrant).
// Serial chain per quadrant (5 barrier rounds after gather):
//   A  : fused sites 0-3 closed form (scalar-lane edge structure)
//   S4 : STEPL site 4 (@27)
//   B  : fused sites 5+6 (STEPC4 output is scalar-lane -> site 6 uses A6[.x])
//   S7 : STEPL site 7 (@27)
//   S8 : STEPL site 8 (@9)
// Merge (R6-proven): rank0/2 pull peer S0 via DSMEM after cluster bar,
// M[v1,v2] = sum_j L.R; rank2 pushes M2 to rank0; rank0 dots, writes.

#define NTH 256
#define ATF 108

__device__ __forceinline__ float dot3(float4 a, float4 b) {
    return a.x * b.x + a.y * b.y + a.z * b.z;
}

__device__ __forceinline__ uint32_t smem_u32(const void* p) {
    uint32_t a;
    asm("{ .reg .u64 t; cvta.to.shared.u64 t, %1; cvt.u32.u64 %0, t; }"
        : "=r"(a) : "l"(p));
    return a;
}

__device__ __forceinline__ float ld_cluster_f32(uint32_t laddr, uint32_t rank) {
    uint32_t r; float v;
    asm volatile("mapa.shared::cluster.u32 %0, %1, %2;" : "=r"(r) : "r"(laddr), "r"(rank));
    asm volatile("ld.shared::cluster.f32 %0, [%1];" : "=f"(v) : "r"(r) : "memory");
    return v;
}

__device__ __forceinline__ void st_cluster_f32(uint32_t laddr, uint32_t rank, float v) {
    uint32_t r;
    asm volatile("mapa.shared::cluster.u32 %0, %1, %2;" : "=r"(r) : "r"(laddr), "r"(rank));
    asm volatile("st.shared::cluster.f32 [%0], %1;" :: "r"(r), "f"(v) : "memory");
}

#define CLUSTER_BAR() do { \
    asm volatile("barrier.cluster.arrive.aligned;" ::: "memory"); \
    asm volatile("barrier.cluster.wait.aligned;"   ::: "memory"); \
} while (0)

__global__ __launch_bounds__(NTH, 1) __cluster_dims__(4, 1, 1)
void peps_quad_kernel(const int* __restrict__ xcfg,
                      const float* __restrict__ T,
                      float* __restrict__ out) {
    __shared__ float4 S0[243];
    __shared__ float4 S1[243];
    __shared__ float  At[9 * ATF];
    __shared__ float  M[729];
    __shared__ float  M2[729];
    __shared__ int    sOff[36];
    __shared__ float  red[8];

    const int t = threadIdx.x;
    const int b = blockIdx.x >> 2;
    uint32_t rank;
    asm("mov.u32 %0, %%cluster_ctarank;" : "=r"(rank));
    const int bottom = (int)(rank >> 1);
    const int right  = (int)(rank & 1);

    // sOff straight from gmem (no spins-SMEM pass, one fewer sync)
    if (t < 36) {
        const int* xb = xcfg + b * 36;
        int xx = t / 6, yy = t % 6;
        int p  = xb[t];
        int pu = (xx > 0) ? xb[t - 6] : 0;
        int pd = (xx < 5) ? xb[t + 6] : 0;
        int pl = (yy > 0) ? xb[t - 1] : 0;
        int pr = (yy < 5) ? xb[t + 1] : 0;
        sOff[t] = (((p * 2 + pu) * 2 + pd) * 2 + pl) * 2 + pr;
    }
    __syncthreads();

    // Gather my quadrant's 9 site tensors: At[s][o][hp][a][ln].
    for (int i = t; i < 9 * ATF; i += NTH) {
        int s = i / ATF, r = i - s * ATF;
        int o  = r / 36;  r -= o * 36;
        int hp = r / 12;  r -= hp * 12;
        int a  = r >> 2,  ln = r & 3;
        float v = 0.0f;
        if (ln < 3) {
            int x = bottom ? 5 - s / 3 : s / 3;
            int y = right  ? 5 - s % 3 : s % 3;
            int u  = bottom ? o : a;
            int d  = bottom ? a : o;
            int l  = right ? hp : ln;
            int rr = right ? ln : hp;
            int site = x * 6 + y;
            v = T[site * 2592 + (((u * 3 + d) * 3 + l) * 3 + rr) * 32 + sOff[site]];
        }
        At[i] = v;
    }
    __syncthreads();

    // hoisted per-thread step indices
    const int d81 = t / 81;
    const int d27 = (t / 27) % 3,  b27 = t - d27 * 27;
    const int d9  = (t / 9) % 3,   b9  = t - d9 * 9;
    const int r3  = t % 3;
    const int m3  = (t / 3) % 3;
    const int c27 = (t % 81) / 27;

    const float4* Atv = (const float4*)At;

    // Step A: fused sites 0-3. out(t) nonzero only for t%3==0:
    //   g_h1 = sum_h2 A1[d1,h2,h1]*A2[d2,r2,h2];  v_u = sum_h1 A0[u,h1]*g_h1
    //   r_hp = sum_u v_u * A3[d81][hp][u][ln=0]
    if (t < 243) {
        float4 vout = make_float4(0.0f, 0.0f, 0.0f, 0.0f);
        if (r3 == 0) {
            int d1 = d27, d2 = d9, r2 = m3;
            const float* A1 = At + ATF + d1 * 36;
            const float* A2 = At + 2 * ATF + d2 * 36 + r2 * 12;
            float g0 = A1[0] * A2[0] + A1[12] * A2[1] + A1[24] * A2[2];
            float g1 = A1[1] * A2[0] + A1[13] * A2[1] + A1[25] * A2[2];
            float g2 = A1[2] * A2[0] + A1[14] * A2[1] + A1[26] * A2[2];
            float v0 = At[0]  * g0 + At[12] * g1 + At[24] * g2;
            float v1 = At[36] * g0 + At[48] * g1 + At[60] * g2;
            float v2 = At[72] * g0 + At[84] * g1 + At[96] * g2;
            const float* A3 = At + 3 * ATF + d81 * 36;
            vout.x = v0 * A3[0]  + v1 * A3[4]  + v2 * A3[8];
            vout.y = v0 * A3[12] + v1 * A3[16] + v2 * A3[20];
            vout.z = v0 * A3[24] + v1 * A3[28] + v2 * A3[32];
        }
        S0[t] = vout;
    }
    __syncthreads();

#define STEPL(SITE, D_, BASE, S3, RD, WR) { \
    if (t < 243) { \
        float4 c0 = (RD)[BASE]; \
        float4 c1 = (RD)[BASE + (S3)]; \
        float4 c2 = (RD)[BASE + 2 * (S3)]; \
        const float4* Av = Atv + (SITE) * 27 + (D_) * 9; \
        float r0 = dot3(c0, Av[0]) + dot3(c1, Av[1]) + dot3(c2, Av[2]); \
        float r1 = dot3(c0, Av[3]) + dot3(c1, Av[4]) + dot3(c2, Av[5]); \
        float r2 = dot3(c0, Av[6]) + dot3(c1, Av[7]) + dot3(c2, Av[8]); \
        (WR)[t] = make_float4(r0, r1, r2, 0.0f); \
    } \
    __syncthreads(); \
}

    // S4: site 4 (@27)
    STEPL(4, d27, b27, 27, S0, S1)

    // Step B: fused sites 5+6. For output t:
    //   s[u6] = sum_u dot3(S4[(u6*3+c27)*27 + m3*3 + 9u], A5v[d9*9+r3*3+u])
    //   r_hp  = sum_u6 s[u6] * A6[d81][hp][u6][ln=0]
    if (t < 243) {
        const float4* A5v = Atv + 5 * 27 + d9 * 9 + r3 * 3;
        float4 a50 = A5v[0], a51 = A5v[1], a52 = A5v[2];
        float s0, s1, s2;
        {
            int base = c27 * 27 + m3 * 3;
            s0 = dot3(S1[base], a50) + dot3(S1[base + 9], a51) + dot3(S1[base + 18], a52);
            base += 81;
            s1 = dot3(S1[base], a50) + dot3(S1[base + 9], a51) + dot3(S1[base + 18], a52);
            base += 81;
            s2 = dot3(S1[base], a50) + dot3(S1[base + 9], a51) + dot3(S1[base + 18], a52);
        }
        const float* A6 = At + 6 * ATF + d81 * 36;
        S0[t] = make_float4(
            s0 * A6[0]  + s1 * A6[4]  + s2 * A6[8],
            s0 * A6[12] + s1 * A6[16] + s2 * A6[20],
            s0 * A6[24] + s1 * A6[28] + s2 * A6[32], 0.0f);
    }
    __syncthreads();

    // S7 (@27), S8 (@9)
    STEPL(7, d27, b27, 27, S0, S1)
    STEPL(8, d9,  b9,   9, S1, S0)   // final state in S0
#undef STEPL

    CLUSTER_BAR();

    // Ranks 0 (top) and 2 (bottom): pull peer quadrant (rank+1) and merge.
    if (right == 0) {
        float* S1f = (float*)S1;
        uint32_t s0a = smem_u32(S0);
        for (int i = t; i < 972; i += NTH)
            S1f[i] = ld_cluster_f32(s0a + (uint32_t)i * 4u, rank + 1);
        __syncthreads();
        uint32_t m2a = smem_u32(M2);
        for (int v = t; v < 729; v += NTH) {
            int v1 = v / 27, v2 = v - 27 * (v / 27);
            const float4* L = S0 + v1 * 9;
            const float4* R = S1 + v2 * 9;
            float s = 0.0f;
            #pragma unroll
            for (int j = 0; j < 9; ++j) s += dot3(L[j], R[j]);
            if (bottom) st_cluster_f32(m2a + (uint32_t)v * 4u, 0, s);
            else        M[v] = s;
        }
    }
    CLUSTER_BAR();

    if (rank == 0) {
        float s = 0.0f;
        for (int v = t; v < 729; v += NTH) s += M[v] * M2[v];
        #pragma unroll
        for (int o = 16; o; o >>= 1) s += __shfl_xor_sync(0xFFFFFFFFu, s, o);
        if ((t & 31) == 0) red[t >> 5] = s;
        __syncthreads();
        if (t == 0) {
            float tt = 0.0f;
            #pragma unroll
            for (int w = 0; w < 8; ++w) tt += red[w];
            out[b] = tt;
        }
    }
}

extern "C" void kernel_launch(void* const* d_in, const int* in_sizes, int n_in,
                              void* d_out, int out_size) {
    const int*   xcfg = nullptr;
    const float* T    = nullptr;
    for (int i = 0; i < n_in; ++i) {
        if (in_sizes[i] == 576) xcfg = (const int*)d_in[i];
        else                    T    = (const float*)d_in[i];
    }
    float* out = (float*)d_out;
    peps_quad_kernel<<<64, NTH>>>(xcfg, T, out);
}